// round 16
// baseline (speedup 1.0000x reference)
#include <cuda_runtime.h>
#include <cuda_bf16.h>
#include <cstdint>
#include <math.h>

#define EDIM 256
#define NHEAD 8
#define HDIM 32
#define BATCH 4
#define LQ 512
#define LKV 4096
#define NLAYER 4
#define NTQ (LQ*BATCH)
#define NTKV (LKV*BATCH)
#define NBH (BATCH*NHEAD)
#define KSPLIT 16
#define KVCHUNK (LKV/KSPLIT)   // 256
#define QBLK 256
#define EE2 (EDIM*EDIM/2)
#define SCH_C 12599168.0f      // low16(bits(C + 128x)) = bf16(2^x)

// ---------------- scratch (device globals) ----------------
__device__ float g_x  [NTQ*EDIM];
__device__ float g_opart[KSPLIT*NBH*LQ*HDIM];
__device__ float g_lpart[KSPLIT*NBH*LQ];
__device__ float g_t1 [NTQ*EDIM];
__device__ float g_x1 [NTQ*EDIM];
__device__ float g_t2 [NTQ*EDIM];
__device__ uint32_t g_vb [NTKV*EDIM/2];
__device__ uint32_t g_xb [NTQ*EDIM/2];
__device__ uint32_t g_wb [NLAYER*3*EE2];
__device__ uint32_t g_qsp[NBH*LQ*16];
__device__ uint32_t g_kb [NBH*LKV*16];       // K packed bf16 pairs [bh][kv][d/2]
__device__ uint32_t g_vbp[NBH*LKV*16];       // V packed bf16 pairs [bh][kv][d/2]
__device__ uint32_t g_osp_hi[NTQ*128],  g_osp_lo[NTQ*128];
__device__ uint32_t g_x1sp_hi[NTQ*128], g_x1sp_lo[NTQ*128];
__device__ uint32_t g_hhsp_hi[NTQ*128], g_hhsp_lo[NTQ*128];
__device__ uint32_t g_wosp_hi[NLAYER*EE2], g_wosp_lo[NLAYER*EE2];
__device__ uint32_t g_w1sp_hi[NLAYER*EE2], g_w1sp_lo[NLAYER*EE2];
__device__ uint32_t g_w2sp_hi[NLAYER*EE2], g_w2sp_lo[NLAYER*EE2];

__device__ __forceinline__ uint32_t cvt_pair(float f0, float f1){
    uint32_t r;
    asm("cvt.rn.bf16x2.f32 %0, %2, %1;" : "=r"(r) : "f"(f0), "f"(f1));
    return r;
}
__device__ __forceinline__ void split_pack(float f0, float f1, uint32_t& hi, uint32_t& lo){
    __nv_bfloat16 h0 = __float2bfloat16_rn(f0);
    __nv_bfloat16 h1 = __float2bfloat16_rn(f1);
    __nv_bfloat16 l0 = __float2bfloat16_rn(f0 - __bfloat162float(h0));
    __nv_bfloat16 l1 = __float2bfloat16_rn(f1 - __bfloat162float(h1));
    hi = (uint32_t)__bfloat16_as_ushort(h0) | ((uint32_t)__bfloat16_as_ushort(h1) << 16);
    lo = (uint32_t)__bfloat16_as_ushort(l0) | ((uint32_t)__bfloat16_as_ushort(l1) << 16);
}
__device__ __forceinline__ uint32_t prmt_pair(float t0, float t1){
    uint32_t p;
    asm("prmt.b32 %0, %1, %2, 0x5410;" : "=r"(p)
        : "r"(__float_as_uint(t0)), "r"(__float_as_uint(t1)));
    return p;
}
__device__ __forceinline__ uint32_t prmt32(uint32_t a, uint32_t b, uint32_t sel){
    uint32_t p;
    asm("prmt.b32 %0, %1, %2, %3;" : "=r"(p) : "r"(a), "r"(b), "r"(sel));
    return p;
}

__global__ void cvt_kernel(const float* __restrict__ src, uint32_t* __restrict__ dst){
    int i = blockIdx.x*256 + threadIdx.x;
    float4 f = ((const float4*)src)[i];
    ((uint2*)dst)[i] = make_uint2(cvt_pair(f.x, f.y), cvt_pair(f.z, f.w));
}
__global__ void split_kernel(const float* __restrict__ src, uint32_t* __restrict__ hi,
                             uint32_t* __restrict__ lo){
    int i = blockIdx.x*256 + threadIdx.x;
    float4 f = ((const float4*)src)[i];
    uint32_t h0,l0,h1,l1;
    split_pack(f.x, f.y, h0, l0);
    split_pack(f.z, f.w, h1, l1);
    ((uint2*)hi)[i] = make_uint2(h0, h1);
    ((uint2*)lo)[i] = make_uint2(l0, l1);
}

__device__ __forceinline__ void mma16816(float* d, const uint32_t* a, const uint32_t* b){
    asm volatile("mma.sync.aligned.m16n8k16.row.col.f32.bf16.bf16.f32 "
        "{%0,%1,%2,%3}, {%4,%5,%6,%7}, {%8,%9}, {%0,%1,%2,%3};"
        : "+f"(d[0]), "+f"(d[1]), "+f"(d[2]), "+f"(d[3])
        : "r"(a[0]), "r"(a[1]), "r"(a[2]), "r"(a[3]), "r"(b[0]), "r"(b[1]));
}

// ================= single-bf16 projection GEMM (128x128 tile) =================
// OUTM 0: Q -> rope+scale -> packed pairs; OUTM 1: fused KV -> BOTH packed pairs (K rope'd)
template<int OUTM>
__global__ __launch_bounds__(256)
void gemm_bf16(const uint32_t* __restrict__ A, const uint32_t* __restrict__ B,
               const float* __restrict__ bias, const float* __restrict__ pos,
               uint32_t* __restrict__ opk, uint32_t* __restrict__ opv, int L, float scale)
{
    __shared__ uint32_t AS[16][136];
    __shared__ uint32_t BS[16][136];

    const int tid  = threadIdx.x;
    const int warp = tid >> 5;
    const int lane = tid & 31;
    const int g    = lane >> 2;
    const int tig  = lane & 3;
    const int wm   = warp >> 2;
    const int wn   = warp & 3;
    const int row0 = blockIdx.x * 128;
    const int col0 = blockIdx.y * 128;

    float acc[4][4][4];
#pragma unroll
    for (int i = 0; i < 4; i++)
#pragma unroll
        for (int n = 0; n < 4; n++)
#pragma unroll
            for (int x = 0; x < 4; x++) acc[i][n][x] = 0.f;

    const int r   = tid >> 1;
    const int kpb = (tid & 1) * 8;

    for (int k0 = 0; k0 < EDIM; k0 += 32) {
        __syncthreads();
        {
            size_t aoff = (size_t)(row0 + r)*(EDIM/2) + (k0 >> 1) + kpb;
            size_t boff = (size_t)(col0 + r)*(EDIM/2) + (k0 >> 1) + kpb;
            uint4 a0 = *(const uint4*)(A + aoff);
            uint4 a1 = *(const uint4*)(A + aoff + 4);
            AS[kpb+0][r]=a0.x; AS[kpb+1][r]=a0.y; AS[kpb+2][r]=a0.z; AS[kpb+3][r]=a0.w;
            AS[kpb+4][r]=a1.x; AS[kpb+5][r]=a1.y; AS[kpb+6][r]=a1.z; AS[kpb+7][r]=a1.w;
            uint4 b0 = *(const uint4*)(B + boff);
            uint4 b1 = *(const uint4*)(B + boff + 4);
            BS[kpb+0][r]=b0.x; BS[kpb+1][r]=b0.y; BS[kpb+2][r]=b0.z; BS[kpb+3][r]=b0.w;
            BS[kpb+4][r]=b1.x; BS[kpb+5][r]=b1.y; BS[kpb+6][r]=b1.z; BS[kpb+7][r]=b1.w;
        }
        __syncthreads();

#pragma unroll
        for (int kc = 0; kc < 2; kc++) {
            uint32_t bf[4][2];
#pragma unroll
            for (int n = 0; n < 4; n++) {
                int c = wn*32 + n*8 + g;
                bf[n][0] = BS[kc*8 + tig    ][c];
                bf[n][1] = BS[kc*8 + 4 + tig][c];
            }
#pragma unroll
            for (int i = 0; i < 4; i++) {
                uint32_t af[4];
#pragma unroll
                for (int part = 0; part < 4; part++) {
                    int rr = wm*64 + i*16 + g + (part & 1)*8;
                    int kp = kc*8 + (part >> 1)*4 + tig;
                    af[part] = AS[kp][rr];
                }
#pragma unroll
                for (int n = 0; n < 4; n++)
                    mma16816(acc[i][n], af, bf[n]);
            }
        }
    }

#pragma unroll
    for (int i = 0; i < 4; i++) {
#pragma unroll
        for (int n = 0; n < 4; n++) {
            int c  = col0 + wn*32 + n*8 + tig*2;
            float b0 = bias[c], b1 = bias[c+1];
#pragma unroll
            for (int hf = 0; hf < 2; hf++) {
                int t  = row0 + wm*64 + i*16 + g + hf*8;
                int l  = t >> 2;
                int bb = t & 3;
                float v0 = (acc[i][n][hf*2+0] + b0) * scale;
                float v1 = (acc[i][n][hf*2+1] + b1) * scale;
                if (OUTM == 0 || c < EDIM) {   // Q or K: rope + packed-pair store
                    const float* pp = pos + ((size_t)(bb*L + l)*EDIM + c)*2;
                    float4 cs = *(const float4*)pp;
                    float ve = v0, vo = v1;
                    v0 = ve*cs.x - vo*cs.y;
                    v1 = vo*cs.z + ve*cs.w;
                    int h = c >> 5, d = c & 31;
                    opk[((size_t)(bb*NHEAD + h)*L + l)*16 + (d >> 1)] = cvt_pair(v0, v1);
                } else {                        // V: packed pairs
                    int cv = c - EDIM;
                    int h = cv >> 5, d = cv & 31;
                    opv[((size_t)(bb*NHEAD + h)*L + l)*16 + (d >> 1)] = cvt_pair(v0, v1);
                }
            }
        }
    }
}

// ================= 2-term-split tc GEMM, 64x64 tile (Wo/FFN) =================
template<int MODE>
__global__ __launch_bounds__(256)
void gemm_tc64(const uint32_t* __restrict__ Ahi, const uint32_t* __restrict__ Alo,
               const uint32_t* __restrict__ Bhi, const uint32_t* __restrict__ Blo,
               const float* __restrict__ bias, const float* __restrict__ res,
               float* __restrict__ outf, uint32_t* __restrict__ ohi, uint32_t* __restrict__ olo)
{
    __shared__ uint32_t AS[2][16][68];
    __shared__ uint32_t BS[2][16][68];

    const int tid  = threadIdx.x;
    const int warp = tid >> 5;
    const int lane = tid & 31;
    const int g    = lane >> 2;
    const int tig  = lane & 3;
    const int wm   = warp >> 2;
    const int wn   = warp & 3;
    const int row0 = blockIdx.x * 64;
    const int col0 = blockIdx.y * 64;

    float acc[2][2][4];
#pragma unroll
    for (int i = 0; i < 2; i++)
#pragma unroll
        for (int n = 0; n < 2; n++)
#pragma unroll
            for (int x = 0; x < 4; x++) acc[i][n][x] = 0.f;

    const int r   = tid >> 2;
    const int kpb = (tid & 3) * 4;

    for (int k0 = 0; k0 < EDIM; k0 += 32) {
        __syncthreads();
        {
            size_t aoff = (size_t)(row0 + r)*(EDIM/2) + (k0 >> 1) + kpb;
            size_t boff = (size_t)(col0 + r)*(EDIM/2) + (k0 >> 1) + kpb;
            uint4 a0 = *(const uint4*)(Ahi + aoff);
            AS[0][kpb+0][r]=a0.x; AS[0][kpb+1][r]=a0.y; AS[0][kpb+2][r]=a0.z; AS[0][kpb+3][r]=a0.w;
            uint4 a1 = *(const uint4*)(Alo + aoff);
            AS[1][kpb+0][r]=a1.x; AS[1][kpb+1][r]=a1.y; AS[1][kpb+2][r]=a1.z; AS[1][kpb+3][r]=a1.w;
            uint4 b0 = *(const uint4*)(Bhi + boff);
            BS[0][kpb+0][r]=b0.x; BS[0][kpb+1][r]=b0.y; BS[0][kpb+2][r]=b0.z; BS[0][kpb+3][r]=b0.w;
            uint4 b1 = *(const uint4*)(Blo + boff);
            BS[1][kpb+0][r]=b1.x; BS[1][kpb+1][r]=b1.y; BS[1][kpb+2][r]=b1.z; BS[1][kpb+3][r]=b1.w;
        }
        __syncthreads();

#pragma unroll
        for (int kc = 0; kc < 2; kc++) {
            uint32_t bh[2][2], bl[2][2];
#pragma unroll
            for (int n = 0; n < 2; n++) {
                int c = wn*16 + n*8 + g;
                bh[n][0] = BS[0][kc*8 + tig    ][c];
                bh[n][1] = BS[0][kc*8 + 4 + tig][c];
                bl[n][0] = BS[1][kc*8 + tig    ][c];
                bl[n][1] = BS[1][kc*8 + 4 + tig][c];
            }
#pragma unroll
            for (int i = 0; i < 2; i++) {
                uint32_t ah[4], al[4];
#pragma unroll
                for (int part = 0; part < 4; part++) {
                    int rr = wm*32 + i*16 + g + (part & 1)*8;
                    int kp = kc*8 + (part >> 1)*4 + tig;
                    ah[part] = AS[0][kp][rr];
                    al[part] = AS[1][kp][rr];
                }
#pragma unroll
                for (int n = 0; n < 2; n++) {
                    mma16816(acc[i][n], ah, bh[n]);
                    mma16816(acc[i][n], ah, bl[n]);
                    mma16816(acc[i][n], al, bh[n]);
                }
            }
        }
    }

#pragma unroll
    for (int i = 0; i < 2; i++) {
#pragma unroll
        for (int n = 0; n < 2; n++) {
            int c  = col0 + wn*16 + n*8 + tig*2;
            float b0 = bias[c], b1 = bias[c+1];
#pragma unroll
            for (int hf = 0; hf < 2; hf++) {
                int t = row0 + wm*32 + i*16 + g + hf*8;
                float v0 = acc[i][n][hf*2+0] + b0;
                float v1 = acc[i][n][hf*2+1] + b1;
                if (MODE == 0) {
                    float2 rr = *(const float2*)(res + (size_t)t*EDIM + c);
                    *(float2*)(outf + (size_t)t*EDIM + c) = make_float2(v0 + rr.x, v1 + rr.y);
                } else {
                    v0 = fmaxf(v0, 0.f);
                    v1 = fmaxf(v1, 0.f);
                    uint32_t ph, pl;
                    split_pack(v0, v1, ph, pl);
                    ohi[(size_t)t*128 + (c >> 1)] = ph;
                    olo[(size_t)t*128 + (c >> 1)] = pl;
                }
            }
        }
    }
}

// ===== split-KV flash attention: packed K+V, MMA-folded exp, 256 q rows/CTA =====
__global__ __launch_bounds__(256)
void attn_mma10(const uint32_t* __restrict__ q, const uint32_t* __restrict__ Kp,
                const uint32_t* __restrict__ Vp, float* __restrict__ Opart,
                float* __restrict__ Lpart)
{
    __shared__ uint32_t KS[2][16][72];
    __shared__ uint32_t VS[2][32][40];

    const int tid  = threadIdx.x;
    const int warp = tid >> 5;
    const int lane = tid & 31;
    const int g    = lane >> 2;
    const int tig  = lane & 3;
    const int bh   = blockIdx.y;
    const int q0   = blockIdx.x * QBLK;
    const int sp   = blockIdx.z;
    const int kvb  = sp * KVCHUNK;

    uint32_t qa[2][2][4];
#pragma unroll
    for (int m = 0; m < 2; m++)
#pragma unroll
        for (int kc = 0; kc < 2; kc++)
#pragma unroll
            for (int part = 0; part < 4; part++) {
                int r = q0 + warp*32 + m*16 + g + (part & 1)*8;
                qa[m][kc][part] = q[((size_t)bh*LQ + r)*16 + kc*8 + (part >> 1)*4 + tig];
            }

    float oacc[2][4][4];
#pragma unroll
    for (int m = 0; m < 2; m++)
#pragma unroll
        for (int n = 0; n < 4; n++)
#pragma unroll
            for (int x = 0; x < 4; x++) oacc[m][n][x] = 0.f;
    float oe[2][4];
    oe[0][0]=oe[0][1]=oe[0][2]=oe[0][3]=0.f;
    oe[1][0]=oe[1][1]=oe[1][2]=oe[1][3]=0.f;
    const uint32_t onesf[2] = {0x3F803F80u, 0x3F803F80u};

    const int kr4 = tid >> 2, kc4 = (tid & 3) * 4;   // K loader
    const int vkp = tid >> 3, vds = (tid & 7) * 4;   // V loader (kv pair, d base)
    const uint32_t* kpk = Kp + (size_t)bh*LKV*16;
    const uint32_t* vpk = Vp + (size_t)bh*LKV*16;

    {
        uint4 kv4 = *(const uint4*)(kpk + (size_t)(kvb + kr4)*16 + kc4);
        uint2 a = *(const uint2*)(vpk + (size_t)(kvb + 2*vkp)*16 + (vds >> 1));
        uint2 b = *(const uint2*)(vpk + (size_t)(kvb + 2*vkp + 1)*16 + (vds >> 1));
        KS[0][kc4+0][kr4]=kv4.x; KS[0][kc4+1][kr4]=kv4.y;
        KS[0][kc4+2][kr4]=kv4.z; KS[0][kc4+3][kr4]=kv4.w;
        VS[0][vkp][vds+0] = prmt32(a.x, b.x, 0x5410);
        VS[0][vkp][vds+1] = prmt32(a.x, b.x, 0x7632);
        VS[0][vkp][vds+2] = prmt32(a.y, b.y, 0x5410);
        VS[0][vkp][vds+3] = prmt32(a.y, b.y, 0x7632);
    }
    __syncthreads();

    const int NT = KVCHUNK/64;
#pragma unroll 1
    for (int t = 0; t < NT; t++) {
        const int cur = t & 1, nxt = cur ^ 1;
        uint4 kv4;
        uint2 va, vb2;
        if (t + 1 < NT) {
            kv4 = *(const uint4*)(kpk + (size_t)(kvb + (t+1)*64 + kr4)*16 + kc4);
            va  = *(const uint2*)(vpk + (size_t)(kvb + (t+1)*64 + 2*vkp)*16 + (vds >> 1));
            vb2 = *(const uint2*)(vpk + (size_t)(kvb + (t+1)*64 + 2*vkp + 1)*16 + (vds >> 1));
        }

#pragma unroll
        for (int m = 0; m < 2; m++) {
            float sc[8][4];
#pragma unroll
            for (int j = 0; j < 8; j++)
#pragma unroll
                for (int x = 0; x < 4; x++) sc[j][x] = SCH_C;
#pragma unroll
            for (int kc = 0; kc < 2; kc++) {
#pragma unroll
                for (int j = 0; j < 8; j++) {
                    uint32_t bf[2] = { KS[cur][kc*8+tig][j*8+g], KS[cur][kc*8+4+tig][j*8+g] };
                    mma16816(sc[j], qa[m][kc], bf);
                }
            }
#pragma unroll
            for (int kc = 0; kc < 4; kc++) {
                uint32_t pa[4];
                pa[0] = prmt_pair(sc[2*kc][0],   sc[2*kc][1]);
                pa[1] = prmt_pair(sc[2*kc][2],   sc[2*kc][3]);
                pa[2] = prmt_pair(sc[2*kc+1][0], sc[2*kc+1][1]);
                pa[3] = prmt_pair(sc[2*kc+1][2], sc[2*kc+1][3]);
#pragma unroll
                for (int n = 0; n < 4; n++) {
                    uint32_t vf[2] = { VS[cur][kc*8+tig][n*8+g], VS[cur][kc*8+4+tig][n*8+g] };
                    mma16816(oacc[m][n], pa, vf);
                }
                mma16816(oe[m], pa, onesf);
            }
        }

        if (t + 1 < NT) {
            KS[nxt][kc4+0][kr4]=kv4.x; KS[nxt][kc4+1][kr4]=kv4.y;
            KS[nxt][kc4+2][kr4]=kv4.z; KS[nxt][kc4+3][kr4]=kv4.w;
            VS[nxt][vkp][vds+0] = prmt32(va.x, vb2.x, 0x5410);
            VS[nxt][vkp][vds+1] = prmt32(va.x, vb2.x, 0x7632);
            VS[nxt][vkp][vds+2] = prmt32(va.y, vb2.y, 0x5410);
            VS[nxt][vkp][vds+3] = prmt32(va.y, vb2.y, 0x7632);
            __syncthreads();
        }
    }

#pragma unroll
    for (int m = 0; m < 2; m++) {
        float* ob = Opart + (((size_t)sp*NBH + bh)*LQ + q0 + warp*32 + m*16)*HDIM;
#pragma unroll
        for (int n = 0; n < 4; n++) {
            int c = n*8 + tig*2;
            *(float2*)(ob + (size_t)g*HDIM + c)     = make_float2(oacc[m][n][0], oacc[m][n][1]);
            *(float2*)(ob + (size_t)(g+8)*HDIM + c) = make_float2(oacc[m][n][2], oacc[m][n][3]);
        }
        if (tig == 0) {
            float* lb = Lpart + ((size_t)sp*NBH + bh)*LQ + q0 + warp*32 + m*16;
            lb[g]     = oe[m][0];
            lb[g + 8] = oe[m][2];
        }
    }
}

// combine: sum partials, normalize, emit SPLIT pairs in [t][e/2]
__global__ void attn_combine(const float* __restrict__ Op, const float* __restrict__ Lp,
                             uint32_t* __restrict__ ohi, uint32_t* __restrict__ olo)
{
    int i = blockIdx.x*256 + threadIdx.x;
    int e = i & 255, t = i >> 8;
    int l = t >> 2, bb = t & 3;
    int h = e >> 5, d = e & 31;
    int bh = bb*NHEAD + h;
    size_t oidx = ((size_t)bh*LQ + l)*HDIM + d;
    size_t lidx = (size_t)bh*LQ + l;
    float s = 0.f, ls = 0.f;
#pragma unroll
    for (int sp = 0; sp < KSPLIT; sp++) {
        s  += Op[(size_t)sp*NBH*LQ*HDIM + oidx];
        ls += Lp[(size_t)sp*NBH*LQ + lidx];
    }
    float o = s / ls;
    float o1 = __shfl_down_sync(0xffffffffu, o, 1);
    if ((e & 1) == 0) {
        uint32_t ph, pl;
        split_pack(o, o1, ph, pl);
        ohi[i >> 1] = ph;
        olo[i >> 1] = pl;
    }
}

// ---- layernorm: one warp per row, 8 rows/block ----
template<int PM>
__global__ __launch_bounds__(256)
void ln_warp(const float* __restrict__ x, const float* __restrict__ gw,
             const float* __restrict__ bw, float* __restrict__ out1,
             float* __restrict__ out2, uint32_t* __restrict__ phi,
             uint32_t* __restrict__ plo)
{
    const int warp = threadIdx.x >> 5, lane = threadIdx.x & 31;
    const int t = blockIdx.x*8 + warp;
    const float* xr = x + (size_t)t*EDIM;

    float4 v0 = ((const float4*)xr)[lane*2];
    float4 v1 = ((const float4*)xr)[lane*2 + 1];
    float s1 = v0.x+v0.y+v0.z+v0.w + v1.x+v1.y+v1.z+v1.w;
    float s2 = v0.x*v0.x+v0.y*v0.y+v0.z*v0.z+v0.w*v0.w
             + v1.x*v1.x+v1.y*v1.y+v1.z*v1.z+v1.w*v1.w;
#pragma unroll
    for (int off = 16; off; off >>= 1) {
        s1 += __shfl_xor_sync(0xffffffffu, s1, off);
        s2 += __shfl_xor_sync(0xffffffffu, s2, off);
    }
    float mean = s1 * (1.f/EDIM);
    float var  = s2 * (1.f/EDIM) - mean*mean;
    float inv  = rsqrtf(var + 1e-5f);

    float4 g0 = ((const float4*)gw)[lane*2];
    float4 g1 = ((const float4*)gw)[lane*2 + 1];
    float4 b0 = ((const float4*)bw)[lane*2];
    float4 b1 = ((const float4*)bw)[lane*2 + 1];

    float y[8];
    y[0] = (v0.x-mean)*inv*g0.x + b0.x;
    y[1] = (v0.y-mean)*inv*g0.y + b0.y;
    y[2] = (v0.z-mean)*inv*g0.z + b0.z;
    y[3] = (v0.w-mean)*inv*g0.w + b0.w;
    y[4] = (v1.x-mean)*inv*g1.x + b1.x;
    y[5] = (v1.y-mean)*inv*g1.y + b1.y;
    y[6] = (v1.z-mean)*inv*g1.z + b1.z;
    y[7] = (v1.w-mean)*inv*g1.w + b1.w;

    float* o1 = out1 + (size_t)t*EDIM;
    ((float4*)o1)[lane*2]     = make_float4(y[0],y[1],y[2],y[3]);
    ((float4*)o1)[lane*2 + 1] = make_float4(y[4],y[5],y[6],y[7]);
    if (PM == 2) {
        float* o2 = out2 + (size_t)t*EDIM;
        ((float4*)o2)[lane*2]     = make_float4(y[0],y[1],y[2],y[3]);
        ((float4*)o2)[lane*2 + 1] = make_float4(y[4],y[5],y[6],y[7]);
    }

    if (PM == 1) {
        uint32_t ph[4], pl[4];
#pragma unroll
        for (int j = 0; j < 4; j++) split_pack(y[2*j], y[2*j+1], ph[j], pl[j]);
        ((uint4*)(phi + (size_t)t*128))[lane] = make_uint4(ph[0],ph[1],ph[2],ph[3]);
        ((uint4*)(plo + (size_t)t*128))[lane] = make_uint4(pl[0],pl[1],pl[2],pl[3]);
    } else {
        uint32_t pb[4];
#pragma unroll
        for (int j = 0; j < 4; j++) pb[j] = cvt_pair(y[2*j], y[2*j+1]);
        ((uint4*)(phi + (size_t)t*128))[lane] = make_uint4(pb[0],pb[1],pb[2],pb[3]);
    }
}

// ---------------- launch ----------------
extern "C" void kernel_launch(void* const* d_in, const int* in_sizes, int n_in,
                              void* d_out, int out_size)
{
    (void)in_sizes; (void)n_in; (void)out_size;
    const float* query = (const float*)d_in[0];
    const float* value = (const float*)d_in[1];
    const float* qpos  = (const float*)d_in[2];
    const float* vpos  = (const float*)d_in[3];
    const float* Wqkv  = (const float*)d_in[4];
    const float* bqkv  = (const float*)d_in[5];
    const float* Wo    = (const float*)d_in[6];
    const float* bo    = (const float*)d_in[7];
    const float* ln1g  = (const float*)d_in[8];
    const float* ln1b  = (const float*)d_in[9];
    const float* W1    = (const float*)d_in[10];
    const float* b1    = (const float*)d_in[11];
    const float* W2    = (const float*)d_in[12];
    const float* b2    = (const float*)d_in[13];
    const float* ln2g  = (const float*)d_in[14];
    const float* ln2b  = (const float*)d_in[15];
    float* out = (float*)d_out;

#define GETSYM(var, sym, type) void* var##_; cudaGetSymbolAddress(&var##_, sym); type* var = (type*)var##_
    GETSYM(px,   g_x,   float);
    GETSYM(pop,  g_opart, float);
    GETSYM(plp,  g_lpart, float);
    GETSYM(pt1,  g_t1,  float);
    GETSYM(px1,  g_x1,  float);
    GETSYM(pt2,  g_t2,  float);
    GETSYM(vb,  g_vb,  uint32_t);
    GETSYM(xb,  g_xb,  uint32_t);
    GETSYM(wb,  g_wb,  uint32_t);
    GETSYM(qsp, g_qsp, uint32_t);
    GETSYM(kb,  g_kb,  uint32_t);
    GETSYM(vbp, g_vbp, uint32_t);
    GETSYM(osp_hi, g_osp_hi, uint32_t);   GETSYM(osp_lo, g_osp_lo, uint32_t);
    GETSYM(x1sp_hi, g_x1sp_hi, uint32_t); GETSYM(x1sp_lo, g_x1sp_lo, uint32_t);
    GETSYM(hhsp_hi, g_hhsp_hi, uint32_t); GETSYM(hhsp_lo, g_hhsp_lo, uint32_t);
    GETSYM(wosp_hi, g_wosp_hi, uint32_t); GETSYM(wosp_lo, g_wosp_lo, uint32_t);
    GETSYM(w1sp_hi, g_w1sp_hi, uint32_t); GETSYM(w1sp_lo, g_w1sp_lo, uint32_t);
    GETSYM(w2sp_hi, g_w2sp_hi, uint32_t); GETSYM(w2sp_lo, g_w2sp_lo, uint32_t);
#undef GETSYM

    // ---- once-per-launch prep ----
    cvt_kernel<<<NTKV*EDIM/4/256, 256>>>(value, vb);
    cvt_kernel<<<NTQ*EDIM/4/256, 256>>>(query, xb);
    cvt_kernel<<<NLAYER*3*EDIM*EDIM/4/256, 256>>>(Wqkv, wb);
    split_kernel<<<NLAYER*EDIM*EDIM/4/256, 256>>>(Wo, wosp_hi, wosp_lo);
    split_kernel<<<NLAYER*EDIM*EDIM/4/256, 256>>>(W1, w1sp_hi, w1sp_lo);
    split_kernel<<<NLAYER*EDIM*EDIM/4/256, 256>>>(W2, w2sp_hi, w2sp_lo);

    const float LOG2E = 1.4426950408889634f;
    const float qscale = 0.17677669529663687f * LOG2E * 128.0f;
    for (int l = 0; l < NLAYER; l++) {
        const uint32_t* wql = wb + (size_t)l*3*EE2;
        const float* bq = bqkv + (size_t)l*3*EDIM;
        const float* bk = bq + EDIM;
        const float* resid = (l == 0) ? query : px;

        gemm_bf16<0><<<dim3(NTQ/128, 2), 256>>>(xb, wql, bq, qpos,
            qsp, nullptr, LQ, qscale);
        gemm_bf16<1><<<dim3(NTKV/128, 4), 256>>>(vb, wql + EE2, bk, vpos,
            kb, vbp, LKV, 1.0f);

        attn_mma10<<<dim3(LQ/QBLK, NBH, KSPLIT), 256>>>(qsp, kb, vbp, pop, plp);
        attn_combine<<<NTQ*EDIM/256, 256>>>(pop, plp, osp_hi, osp_lo);

        gemm_tc64<0><<<dim3(NTQ/64, 4), 256>>>(osp_hi, osp_lo,
            wosp_hi + (size_t)l*EE2, wosp_lo + (size_t)l*EE2, bo + l*EDIM, resid, pt1, nullptr, nullptr);
        ln_warp<1><<<NTQ/8, 256>>>(pt1, ln1g + l*EDIM, ln1b + l*EDIM, px1, nullptr, x1sp_hi, x1sp_lo);

        gemm_tc64<1><<<dim3(NTQ/64, 4), 256>>>(x1sp_hi, x1sp_lo,
            w1sp_hi + (size_t)l*EE2, w1sp_lo + (size_t)l*EE2, b1 + l*EDIM, nullptr, nullptr, hhsp_hi, hhsp_lo);
        gemm_tc64<0><<<dim3(NTQ/64, 4), 256>>>(hhsp_hi, hhsp_lo,
            w2sp_hi + (size_t)l*EE2, w2sp_lo + (size_t)l*EE2, b2 + l*EDIM, px1, pt2, nullptr, nullptr);

        ln_warp<2><<<NTQ/8, 256>>>(pt2, ln2g + l*EDIM, ln2b + l*EDIM, px,
            out + (size_t)l*NTQ*EDIM, xb, nullptr);
    }
}